// round 16
// baseline (speedup 1.0000x reference)
#include <cuda_runtime.h>
#include <cuda_bf16.h>
#include <math.h>
#include <stdint.h>

#define TM 32
#define NT 256
#define OBS_LD 52
#define H_LD 260

// ---- byte offsets in dynamic smem (per CTA ~106KB -> 2 CTAs/SM) ----
#define ENC_T 0
#define H1T_B 0          // pi1 out: 8 tiles x 4KB (hi+lo), overlays enc tiles 0-7
#define H2_B  36864      // h2 fp32 [32][260], overlays enc tiles 9-17
#define AENC_H 73728     // 4 A slots x 2KB bf16 hi
#define AENC_L 81920     // lo
#define OBS2_B 90112     // obs [32][52] fp32
#define BIAS_B 96768     // enc layer2 biases, 1728 floats
#define CNST_B 103680    // pi consts
#define SMEM_B 108816

typedef unsigned long long u64;
typedef unsigned int u32;

// fragment-major weights, COALESCED: per (p, n32-group g, k16-step ks) block
// of 512 u32 arranged [q=s>>2][lane][c=s&3]: offset = (s>>2)*128 + lane*4 + (s&3)
// s: 0..7 hi (nt=s>>1, reg=s&1), 8..15 lo. value = pkbf(B[k][n], B[k+1][n]),
// n = g*32 + nt*8 + lane/4, k = ks*16 + reg*8 + 2*(lane%4).
__device__ __align__(16) u32 g_B1f[3 * 8 * 36 * 512];
__device__ __align__(16) u32 g_B2f[3 * 8 * 16 * 512];
__device__ __align__(16) u32 g_eBf[3 * 54 * 2 * 512];

__device__ __forceinline__ float lrelu(float x) { return fmaxf(x, 0.01f * x); }
__device__ __forceinline__ u32 smem_u32(const void* p) {
    u32 a;
    asm("{ .reg .u64 t; cvta.to.shared.u64 t, %1; cvt.u32.u64 %0, t; }" : "=r"(a) : "l"(p));
    return a;
}
__device__ __forceinline__ u32 pkbf(__nv_bfloat16 a, __nv_bfloat16 b) {
    __nv_bfloat162 t(a, b);
    return *(u32*)&t;
}
__device__ __forceinline__ u32 swa(u32 base, int row, int u) {
    return base + row * 64 + ((u ^ ((row >> 1) & 3)) << 4);
}
__device__ __forceinline__ void ldm_x4(u32* r, u32 addr) {
    asm volatile("ldmatrix.sync.aligned.m8n8.x4.shared.b16 {%0,%1,%2,%3}, [%4];"
                 : "=r"(r[0]), "=r"(r[1]), "=r"(r[2]), "=r"(r[3]) : "r"(addr));
}
__device__ __forceinline__ void mma16816(float* d, const u32* a, u32 b0, u32 b1) {
    asm volatile(
        "mma.sync.aligned.m16n8k16.row.col.f32.bf16.bf16.f32 "
        "{%0,%1,%2,%3}, {%4,%5,%6,%7}, {%8,%9}, {%0,%1,%2,%3};"
        : "+f"(d[0]), "+f"(d[1]), "+f"(d[2]), "+f"(d[3])
        : "r"(a[0]), "r"(a[1]), "r"(a[2]), "r"(a[3]), "r"(b0), "r"(b1));
}
__device__ __forceinline__ void split2(float v0, float v1, u32& hi, u32& lo) {
    __nv_bfloat16 h0 = __float2bfloat16(v0);
    __nv_bfloat16 h1 = __float2bfloat16(v1);
    hi = pkbf(h0, h1);
    lo = pkbf(__float2bfloat16(v0 - __bfloat162float(h0)),
              __float2bfloat16(v1 - __bfloat162float(h1)));
}
// coalesced fragment-block load: lane's q-th uint4 at block + q*128 + lane*4 (u32)
#define LOADFC(dst, blk, lane)                                        \
    do {                                                              \
        (dst)[0] = *(const uint4*)((blk) + 0 * 128 + (lane) * 4);     \
        (dst)[1] = *(const uint4*)((blk) + 1 * 128 + (lane) * 4);     \
        (dst)[2] = *(const uint4*)((blk) + 2 * 128 + (lane) * 4);     \
        (dst)[3] = *(const uint4*)((blk) + 3 * 128 + (lane) * 4);     \
    } while (0)

// ---- layer1: [32 rows] x [K->32] + bias + lrelu -> A slot tile (hi/lo bf16)
template <int K>
__device__ __forceinline__ void layer1A(const float* __restrict__ s_obs, int in_off,
                                        const float* __restrict__ W1,
                                        const float* __restrict__ b1,
                                        int slot, char* smc, int tid) {
    const int row = tid & 31;
    const int o0 = (tid >> 5) * 4;
    const float* x = s_obs + row * OBS_LD + in_off;
    float4 b = __ldg((const float4*)(b1 + o0));
    float acc[4] = {b.x, b.y, b.z, b.w};
#pragma unroll
    for (int k = 0; k < K; ++k) {
        float xv = x[k];
        float4 w = __ldg((const float4*)(W1 + k * 32 + o0));
        acc[0] = fmaf(xv, w.x, acc[0]);
        acc[1] = fmaf(xv, w.y, acc[1]);
        acc[2] = fmaf(xv, w.z, acc[2]);
        acc[3] = fmaf(xv, w.w, acc[3]);
    }
    u32 hw[2], lw[2];
    split2(lrelu(acc[0]), lrelu(acc[1]), hw[0], lw[0]);
    split2(lrelu(acc[2]), lrelu(acc[3]), hw[1], lw[1]);
    u32 off = swa(0, row, o0 >> 3) + ((o0 & 4) << 1);
    *(uint2*)(smc + AENC_H + slot * 2048 + off) = make_uint2(hw[0], hw[1]);
    *(uint2*)(smc + AENC_L + slot * 2048 + off) = make_uint2(lw[0], lw[1]);
}

// ======================= HMMA pi GEMM: 8 warps, m16 x n64 per warp ==========
// A: hi/lo bf16 tiles at aBase/aBase+2048, chunk stride 4096 (tile-direct).
// B: fragment blocks register-direct, per-k16-step ping-pong prefetch.
// OT=true: output hi/lo tiles at oBase. OT=false: fp32 sOut.
template <bool OT, int Kt>
__device__ void pi_gemm(u32 aBase, const u32* __restrict__ Bf,
                        const float* __restrict__ sBias,
                        float* __restrict__ sOut, int ldo, u32 oBase,
                        char* smc, u32 sbase, int tid) {
    const int w = tid >> 5, lane = tid & 31;
    const int m0 = (w >> 2) * 16;
    const int gp = (w & 3) * 2;          // first n32 group of this warp
    const int fr = ((lane >> 3) & 1) * 8 + (lane & 7);
    const int fu = lane >> 4;
    const int NKS = Kt >> 4;

    u32 adAh[2], adAl[2];
#pragma unroll
    for (int ks = 0; ks < 2; ++ks) {
        int ua = ks * 2 + fu;
        adAh[ks] = sbase + swa(aBase, m0 + fr, ua);
        adAl[ks] = sbase + swa(aBase + 2048, m0 + fr, ua);
    }
    const u32* bfp0 = Bf + (long)gp * NKS * 512;
    const u32* bfp1 = Bf + (long)(gp + 1) * NKS * 512;

    float d[2][4][4];  // [gq][nt][4]
#pragma unroll
    for (int gq = 0; gq < 2; ++gq)
#pragma unroll
        for (int j = 0; j < 4; ++j)
#pragma unroll
            for (int q = 0; q < 4; ++q) d[gq][j][q] = 0.f;

    __syncthreads();   // A tiles ready

    uint4 bq0[4], bq1[4], bn0[4], bn1[4];
    LOADFC(bq0, bfp0, lane);
    LOADFC(bq1, bfp1, lane);

#pragma unroll
    for (int kb = 0; kb < NKS; ++kb) {
        const int ks = kb & 1;
        const u32 aoff = (u32)((kb >> 1) * 4096);
        // prefetch next k16 block while computing this one
        if (kb + 1 < NKS) {
            const u32* n0 = bfp0 + (kb + 1) * 512;
            const u32* n1 = bfp1 + (kb + 1) * 512;
            LOADFC(bn0, n0, lane);
            LOADFC(bn1, n1, lane);
        }
        u32 ah[4], al[4];
        ldm_x4(ah, adAh[ks] + aoff);
        ldm_x4(al, adAl[ks] + aoff);
        const u32* b0 = (const u32*)bq0;
        const u32* b1 = (const u32*)bq1;
#pragma unroll
        for (int nt = 0; nt < 4; ++nt) {
            mma16816(d[0][nt], ah, b0[2 * nt], b0[2 * nt + 1]);
            mma16816(d[0][nt], ah, b0[8 + 2 * nt], b0[8 + 2 * nt + 1]);
            mma16816(d[0][nt], al, b0[2 * nt], b0[2 * nt + 1]);
            mma16816(d[1][nt], ah, b1[2 * nt], b1[2 * nt + 1]);
            mma16816(d[1][nt], ah, b1[8 + 2 * nt], b1[8 + 2 * nt + 1]);
            mma16816(d[1][nt], al, b1[2 * nt], b1[2 * nt + 1]);
        }
        if (kb + 1 < NKS) {
#pragma unroll
            for (int j = 0; j < 4; ++j) { bq0[j] = bn0[j]; bq1[j] = bn1[j]; }
        }
    }
    __syncthreads();   // all A reads done before output overlays
    // ---- readout
#pragma unroll
    for (int gq = 0; gq < 2; ++gq)
#pragma unroll
        for (int nt = 0; nt < 4; ++nt) {
            int tile = gp + gq;
            int lc = nt * 8 + (lane & 3) * 2;
            int col = tile * 32 + lc;
            int row = m0 + (lane >> 2);
            float2 b = *(const float2*)(sBias + col);
            float v0 = lrelu(d[gq][nt][0] + b.x), v1 = lrelu(d[gq][nt][1] + b.y);
            float v2 = lrelu(d[gq][nt][2] + b.x), v3 = lrelu(d[gq][nt][3] + b.y);
            if (OT) {
                u32 off0 = swa(oBase + tile * 4096, row, lc >> 3) + (lc & 7) * 2;
                u32 off1 = swa(oBase + tile * 4096, row + 8, lc >> 3) + (lc & 7) * 2;
                u32 h0, l0, h1, l1;
                split2(v0, v1, h0, l0);
                split2(v2, v3, h1, l1);
                *(u32*)(smc + off0) = h0;
                *(u32*)(smc + off0 + 2048) = l0;
                *(u32*)(smc + off1) = h1;
                *(u32*)(smc + off1 + 2048) = l1;
            } else {
                *(float2*)(sOut + row * ldo + col) = make_float2(v0, v1);
                *(float2*)(sOut + (row + 8) * ldo + col) = make_float2(v2, v3);
            }
        }
    __syncthreads();
}

// ======================= prep: coalesced fragment-major packing =============
__device__ __forceinline__ u32 fragval(float w0, float w1, int lo) {
    __nv_bfloat16 h0 = __float2bfloat16(w0);
    __nv_bfloat16 h1 = __float2bfloat16(w1);
    if (lo) {
        h0 = __float2bfloat16(w0 - __bfloat162float(h0));
        h1 = __float2bfloat16(w1 - __bfloat162float(h1));
    }
    return pkbf(h0, h1);
}

__global__ void prep_kernel(const float* __restrict__ W1, const float* __restrict__ W2,
                            const float* __restrict__ pW2, const float* __restrict__ eW2,
                            const float* __restrict__ oW2) {
    int i = blockIdx.x * 256 + threadIdx.x;
    if (i < 3 * 8 * 36 * 512) {  // pi1
        int p = i / 147456, r = i % 147456;
        int g = r / 18432; r %= 18432;
        int ks = r / 512; r %= 512;
        int lane = (r >> 2) & 31;
        int s = (r >> 7) * 4 + (r & 3);
        int lo = s >> 3, nt = (s & 7) >> 1, reg = s & 1;
        int n = g * 32 + nt * 8 + (lane >> 2);
        int k = ks * 16 + reg * 8 + 2 * (lane & 3);
        g_B1f[i] = fragval(__ldg(W1 + (p * 576 + k) * 256 + n),
                           __ldg(W1 + (p * 576 + k + 1) * 256 + n), lo);
    }
    if (i < 3 * 8 * 16 * 512) {  // pi2
        int p = i / 65536, r = i % 65536;
        int g = r / 8192; r %= 8192;
        int ks = r / 512; r %= 512;
        int lane = (r >> 2) & 31;
        int s = (r >> 7) * 4 + (r & 3);
        int lo = s >> 3, nt = (s & 7) >> 1, reg = s & 1;
        int n = g * 32 + nt * 8 + (lane >> 2);
        int k = ks * 16 + reg * 8 + 2 * (lane & 3);
        g_B2f[i] = fragval(__ldg(W2 + (p * 256 + k) * 256 + n),
                           __ldg(W2 + (p * 256 + k + 1) * 256 + n), lo);
    }
    if (i < 3 * 54 * 2 * 512) {  // encoder layer2
        int p = i / 55296, r = i % 55296;
        int tile = r / 1024; r %= 1024;
        int ks = r / 512; r %= 512;
        int lane = (r >> 2) & 31;
        int s = (r >> 7) * 4 + (r & 3);
        int lo = s >> 3, nt = (s & 7) >> 1, reg = s & 1;
        int n = nt * 8 + (lane >> 2);
        int k = ks * 16 + reg * 8 + 2 * (lane & 3);
        float w0, w1;
        if (tile < 18) {
            int sn = tile >> 1;
            const float* base = pW2 + ((p * 9 + sn) * 32) * 64 + (tile & 1) * 32 + n;
            w0 = __ldg(base + k * 64);
            w1 = __ldg(base + (k + 1) * 64);
        } else if (tile < 36) {
            int e = (tile - 18) / 9, tt = (tile - 18) % 9;
            const float* base = eW2 + ((p * 2 + e) * 32) * 288 + tt * 32 + n;
            w0 = __ldg(base + k * 288);
            w1 = __ldg(base + (k + 1) * 288);
        } else {
            const float* base = oW2 + (p * 32) * 576 + (tile - 36) * 32 + n;
            w0 = __ldg(base + k * 576);
            w1 = __ldg(base + (k + 1) * 576);
        }
        g_eBf[i] = fragval(w0, w1, lo);
    }
}

// ======================= fused kernel =======================================
__global__ void __launch_bounds__(NT, 2)
mlpac_kernel(const float* __restrict__ obs,
             const float* __restrict__ prop_W1, const float* __restrict__ prop_b1,
             const float* __restrict__ prop_W2, const float* __restrict__ prop_b2,
             const float* __restrict__ ext_W1, const float* __restrict__ ext_b1,
             const float* __restrict__ ext_W2, const float* __restrict__ ext_b2,
             const float* __restrict__ opp_W1, const float* __restrict__ opp_b1,
             const float* __restrict__ opp_W2, const float* __restrict__ opp_b2,
             const float* __restrict__ pi_W1, const float* __restrict__ pi_b1,
             const float* __restrict__ pi_W2, const float* __restrict__ pi_b2,
             const float* __restrict__ pi_W3, const float* __restrict__ pi_b3,
             float* __restrict__ out) {
    extern __shared__ float sm[];
    char* smc = (char*)sm;
    float* s_obs = sm + OBS2_B / 4;
    float* bias_sm = sm + BIAS_B / 4;
    float* cst = sm + CNST_B / 4;
    u32 sbase = smem_u32(sm);

    const int tid = threadIdx.x;
    const int p = blockIdx.y;
    const int row0 = blockIdx.x * TM;

    for (int idx = tid; idx < TM * 12; idx += NT) {
        int r = idx / 12, c = (idx % 12) * 4;
        const float* src = obs + ((long)(row0 + r) * 3 + p) * 48 + c;
        *((float4*)(s_obs + r * OBS_LD + c)) = __ldg((const float4*)src);
    }
    for (int i = tid; i < 576; i += NT) {
        bias_sm[i] = __ldg(prop_b2 + p * 576 + i);
        bias_sm[576 + i] = __ldg(ext_b2 + p * 576 + i);
        bias_sm[1152 + i] = __ldg(opp_b2 + p * 576 + i);
    }
    for (int i = tid; i < 256; i += NT) cst[i] = __ldg(pi_b1 + p * 256 + i);
    for (int i = tid; i < 256; i += NT) cst[256 + i] = __ldg(pi_b2 + p * 256 + i);
    for (int i = tid; i < 768; i += NT) cst[512 + i] = __ldg(pi_W3 + p * 768 + i);
    if (tid < 3) cst[1280 + tid] = __ldg(pi_b3 + p * 3 + tid);

    // ======== encoder: 7 sweeps x 8 tiles; enc stored tile-major ============
    const int ew = tid >> 5;
    const int elane = tid & 31;
    const int efr = ((elane >> 3) & 1) * 8 + (elane & 7);
    const int efu = elane >> 4;
    const u32* ebase = g_eBf + (long)p * 54 * 1024;

    uint4 ebq[8];
    {
        const u32* b0 = ebase + ew * 1024;
        LOADFC(ebq, b0, elane);
        LOADFC(ebq + 4, b0 + 512, elane);
    }
    __syncthreads();   // obs ready

    for (int sweep = 0; sweep < 7; ++sweep) {
        if (sweep == 0) {
#pragma unroll
            for (int s = 0; s < 4; ++s)
                layer1A<2>(s_obs, 2 * s, prop_W1 + p * 576 + s * 64,
                           prop_b1 + p * 288 + s * 32, s, smc, tid);
            __syncthreads();
        } else if (sweep == 1) {
#pragma unroll
            for (int s = 0; s < 4; ++s)
                layer1A<2>(s_obs, 2 * (4 + s), prop_W1 + p * 576 + (4 + s) * 64,
                           prop_b1 + p * 288 + (4 + s) * 32, s, smc, tid);
            __syncthreads();
        } else if (sweep == 2) {
            layer1A<2>(s_obs, 16, prop_W1 + p * 576 + 512, prop_b1 + p * 288 + 256, 0, smc, tid);
            layer1A<6>(s_obs, 18, ext_W1 + p * 384, ext_b1 + p * 64, 1, smc, tid);
            layer1A<6>(s_obs, 24, ext_W1 + p * 384 + 192, ext_b1 + p * 64 + 32, 2, smc, tid);
            layer1A<18>(s_obs, 30, opp_W1 + p * 576, opp_b1 + p * 32, 3, smc, tid);
            __syncthreads();
        }
        int tile = sweep * 8 + ew;
        if (tile < 54) {
            int asl = (tile < 16) ? ((tile >> 1) & 3)
                                  : (tile < 18 ? 0 : (tile < 27 ? 1 : (tile < 36 ? 2 : 3)));
            int etile = (tile < 18) ? tile
                       : (tile < 27 ? tile - 18
                       : (tile < 36 ? 9 + (tile - 27) : tile - 36));
            const u32 tb = (u32)(ENC_T + etile * 4096);
            float d[2][4][4];
#pragma unroll
            for (int mt = 0; mt < 2; ++mt)
#pragma unroll
                for (int j = 0; j < 4; ++j)
#pragma unroll
                    for (int q = 0; q < 4; ++q) d[mt][j][q] = 0.f;
#pragma unroll
            for (int ks = 0; ks < 2; ++ks) {
                int ua = ks * 2 + efu;
                u32 ah[2][4], al[2][4];
#pragma unroll
                for (int mt = 0; mt < 2; ++mt) {
                    ldm_x4(ah[mt], sbase + swa(AENC_H + asl * 2048, mt * 16 + efr, ua));
                    ldm_x4(al[mt], sbase + swa(AENC_L + asl * 2048, mt * 16 + efr, ua));
                }
                const u32* bb = (const u32*)(ebq + ks * 4);
#pragma unroll
                for (int mt = 0; mt < 2; ++mt)
#pragma unroll
                    for (int nt = 0; nt < 4; ++nt) {
                        mma16816(d[mt][nt], ah[mt], bb[2 * nt], bb[2 * nt + 1]);
                        mma16816(d[mt][nt], ah[mt], bb[8 + 2 * nt], bb[8 + 2 * nt + 1]);
                        mma16816(d[mt][nt], al[mt], bb[2 * nt], bb[2 * nt + 1]);
                    }
            }
            {   // prefetch next sweep's fragments
                int ntile = tile + 8;
                if (ntile < 54) {
                    const u32* b0 = ebase + ntile * 1024;
                    LOADFC(ebq, b0, elane);
                    LOADFC(ebq + 4, b0 + 512, elane);
                }
            }
            // ---- readout (tile-major enc)
            if (tile < 36) {
                const bool addm = tile >= 18;
#pragma unroll
                for (int mt = 0; mt < 2; ++mt)
#pragma unroll
                    for (int nt = 0; nt < 4; ++nt) {
                        int lc = nt * 8 + (elane & 3) * 2;
                        int r0 = mt * 16 + (elane >> 2);
                        float2 b = *(const float2*)(bias_sm + tile * 32 + lc);
                        float2 v0 = make_float2(lrelu(d[mt][nt][0] + b.x),
                                                lrelu(d[mt][nt][1] + b.y));
                        float2 v1 = make_float2(lrelu(d[mt][nt][2] + b.x),
                                                lrelu(d[mt][nt][3] + b.y));
                        float* e0 = (float*)(smc + tb + r0 * 128 + lc * 4);
                        float* e1 = (float*)(smc + tb + (r0 + 8) * 128 + lc * 4);
                        if (addm) {
                            float2 o0 = *(float2*)e0, o1 = *(float2*)e1;
                            v0.x += o0.x; v0.y += o0.y; v1.x += o1.x; v1.y += o1.y;
                        }
                        *(float2*)e0 = v0;
                        *(float2*)e1 = v1;
                    }
            } else {
                // opp finalize: enc = prev + lrelu(d + bias); overwrite tile
                // in place with bf16 hi/lo ldmatrix tiles (prev pre-read).
                float2 pv[2][4][2];
#pragma unroll
                for (int mt = 0; mt < 2; ++mt)
#pragma unroll
                    for (int nt = 0; nt < 4; ++nt) {
                        int lc = nt * 8 + (elane & 3) * 2;
                        int r0 = mt * 16 + (elane >> 2);
                        pv[mt][nt][0] = *(float2*)(smc + tb + r0 * 128 + lc * 4);
                        pv[mt][nt][1] = *(float2*)(smc + tb + (r0 + 8) * 128 + lc * 4);
                    }
#pragma unroll
                for (int mt = 0; mt < 2; ++mt)
#pragma unroll
                    for (int nt = 0; nt < 4; ++nt) {
                        int lc = nt * 8 + (elane & 3) * 2;
                        int r0 = mt * 16 + (elane >> 2);
                        float2 b = *(const float2*)(bias_sm + tile * 32 + lc);
                        float v0 = pv[mt][nt][0].x + lrelu(d[mt][nt][0] + b.x);
                        float v1 = pv[mt][nt][0].y + lrelu(d[mt][nt][1] + b.y);
                        float v2 = pv[mt][nt][1].x + lrelu(d[mt][nt][2] + b.x);
                        float v3 = pv[mt][nt][1].y + lrelu(d[mt][nt][3] + b.y);
                        u32 h0, l0, h1, l1;
                        split2(v0, v1, h0, l0);
                        split2(v2, v3, h1, l1);
                        u32 off0 = swa(tb, r0, lc >> 3) + (lc & 7) * 2;
                        u32 off1 = swa(tb, r0 + 8, lc >> 3) + (lc & 7) * 2;
                        *(u32*)(smc + off0) = h0;
                        *(u32*)(smc + off0 + 2048) = l0;
                        *(u32*)(smc + off1) = h1;
                        *(u32*)(smc + off1 + 2048) = l1;
                    }
            }
        }
        __syncthreads();
    }

    // ======== pi MLP (tile-direct A, register-direct B, sync-free) ========
    pi_gemm<true, 576>((u32)ENC_T, g_B1f + (long)p * 147456, cst,
                       (float*)0, 0, (u32)H1T_B, smc, sbase, tid);
    pi_gemm<false, 256>((u32)H1T_B, g_B2f + (long)p * 65536, cst + 256,
                        sm + H2_B / 4, H_LD, 0, smc, sbase, tid);

    if (tid < 96) {
        int row = tid / 3, o = tid - row * 3;
        const float* h2 = sm + H2_B / 4 + row * H_LD;
        float acc = cst[1280 + o];
#pragma unroll 8
        for (int k = 0; k < 256; ++k)
            acc = fmaf(h2[k], cst[512 + k * 3 + o], acc);
        out[((long)(row0 + row) * 3 + p) * 3 + o] = tanhf(acc);
    }
}

extern "C" void kernel_launch(void* const* d_in, const int* in_sizes, int n_in,
                              void* d_out, int out_size) {
    const float* obs = (const float*)d_in[0];
    const float* prop_W1 = (const float*)d_in[1];
    const float* prop_b1 = (const float*)d_in[2];
    const float* prop_W2 = (const float*)d_in[3];
    const float* prop_b2 = (const float*)d_in[4];
    const float* ext_W1 = (const float*)d_in[5];
    const float* ext_b1 = (const float*)d_in[6];
    const float* ext_W2 = (const float*)d_in[7];
    const float* ext_b2 = (const float*)d_in[8];
    const float* opp_W1 = (const float*)d_in[9];
    const float* opp_b1 = (const float*)d_in[10];
    const float* opp_W2 = (const float*)d_in[11];
    const float* opp_b2 = (const float*)d_in[12];
    const float* pi_W1 = (const float*)d_in[13];
    const float* pi_b1 = (const float*)d_in[14];
    const float* pi_W2 = (const float*)d_in[15];
    const float* pi_b2 = (const float*)d_in[16];
    const float* pi_W3 = (const float*)d_in[17];
    const float* pi_b3 = (const float*)d_in[18];
    float* out = (float*)d_out;

    prep_kernel<<<1728, 256>>>(pi_W1, pi_W2, prop_W2, ext_W2, opp_W2);

    cudaFuncSetAttribute(mlpac_kernel, cudaFuncAttributeMaxDynamicSharedMemorySize, SMEM_B);
    dim3 grid(65536 / TM, 3, 1);
    mlpac_kernel<<<grid, NT, SMEM_B>>>(
        obs, prop_W1, prop_b1, prop_W2, prop_b2, ext_W1, ext_b1, ext_W2, ext_b2,
        opp_W1, opp_b1, opp_W2, opp_b2, pi_W1, pi_b1, pi_W2, pi_b2, pi_W3, pi_b3,
        out);
}

// round 17
// speedup vs baseline: 1.0655x; 1.0655x over previous
#include <cuda_runtime.h>
#include <cuda_bf16.h>
#include <math.h>
#include <stdint.h>

#define TM 32
#define NT 256
#define OBS_LD 52
#define H_LD 260

// ---- byte offsets in dynamic smem (per CTA ~106KB -> 2 CTAs/SM) ----
// enc tile-major: 18 tiles x 4KB fp32; opp finalize overwrites each tile
// in place with bf16 hi (2KB) + lo (2KB) ldmatrix tiles.
#define ENC_T 0
#define H1T_B 0          // pi1 out: 8 tiles x 4KB (hi+lo), overlays enc tiles 0-7
#define H2_B  36864      // h2 fp32 [32][260] (33280B), overlays enc tiles 9-17
#define AENC_H 73728     // 4 A slots x 2KB bf16 hi
#define AENC_L 81920     // lo
#define OBS2_B 90112     // obs [32][52] fp32 (6656B)
#define BIAS_B 96768     // enc layer2 biases, 1728 floats (6912B)
#define CNST_B 103680    // pi consts (5132B)
#define SMEM_B 108816

typedef unsigned long long u64;
typedef unsigned int u32;

// fragment-major weights, COALESCED: per (p, n32-group g, k16-step ks) block
// of 512 u32 arranged [q=s>>2][lane][c=s&3]: offset = (s>>2)*128 + lane*4 + (s&3)
// s: 0..7 hi (nt=s>>1, reg=s&1), 8..15 lo. value = pkbf(B[k][n], B[k+1][n]),
// n = g*32 + nt*8 + lane/4, k = ks*16 + reg*8 + 2*(lane%4).
__device__ __align__(16) u32 g_B1f[3 * 8 * 36 * 512];
__device__ __align__(16) u32 g_B2f[3 * 8 * 16 * 512];
__device__ __align__(16) u32 g_eBf[3 * 54 * 2 * 512];

__device__ __forceinline__ float lrelu(float x) { return fmaxf(x, 0.01f * x); }
__device__ __forceinline__ u32 smem_u32(const void* p) {
    u32 a;
    asm("{ .reg .u64 t; cvta.to.shared.u64 t, %1; cvt.u32.u64 %0, t; }" : "=r"(a) : "l"(p));
    return a;
}
__device__ __forceinline__ u32 pkbf(__nv_bfloat16 a, __nv_bfloat16 b) {
    __nv_bfloat162 t(a, b);
    return *(u32*)&t;
}
__device__ __forceinline__ u32 swa(u32 base, int row, int u) {
    return base + row * 64 + ((u ^ ((row >> 1) & 3)) << 4);
}
__device__ __forceinline__ void ldm_x4(u32* r, u32 addr) {
    asm volatile("ldmatrix.sync.aligned.m8n8.x4.shared.b16 {%0,%1,%2,%3}, [%4];"
                 : "=r"(r[0]), "=r"(r[1]), "=r"(r[2]), "=r"(r[3]) : "r"(addr));
}
__device__ __forceinline__ void mma16816(float* d, const u32* a, u32 b0, u32 b1) {
    asm volatile(
        "mma.sync.aligned.m16n8k16.row.col.f32.bf16.bf16.f32 "
        "{%0,%1,%2,%3}, {%4,%5,%6,%7}, {%8,%9}, {%0,%1,%2,%3};"
        : "+f"(d[0]), "+f"(d[1]), "+f"(d[2]), "+f"(d[3])
        : "r"(a[0]), "r"(a[1]), "r"(a[2]), "r"(a[3]), "r"(b0), "r"(b1));
}
__device__ __forceinline__ void split2(float v0, float v1, u32& hi, u32& lo) {
    __nv_bfloat16 h0 = __float2bfloat16(v0);
    __nv_bfloat16 h1 = __float2bfloat16(v1);
    hi = pkbf(h0, h1);
    lo = pkbf(__float2bfloat16(v0 - __bfloat162float(h0)),
              __float2bfloat16(v1 - __bfloat162float(h1)));
}
// coalesced fragment-block load: lane's q-th uint4 at block + q*128 + lane*4 (u32)
#define LOADFC(dst, blk, lane)                                        \
    do {                                                              \
        (dst)[0] = *(const uint4*)((blk) + 0 * 128 + (lane) * 4);     \
        (dst)[1] = *(const uint4*)((blk) + 1 * 128 + (lane) * 4);     \
        (dst)[2] = *(const uint4*)((blk) + 2 * 128 + (lane) * 4);     \
        (dst)[3] = *(const uint4*)((blk) + 3 * 128 + (lane) * 4);     \
    } while (0)

// ---- layer1: [32 rows] x [K->32] + bias + lrelu -> A slot tile (hi/lo bf16)
template <int K>
__device__ __forceinline__ void layer1A(const float* __restrict__ s_obs, int in_off,
                                        const float* __restrict__ W1,
                                        const float* __restrict__ b1,
                                        int slot, char* smc, int tid) {
    const int row = tid & 31;
    const int o0 = (tid >> 5) * 4;
    const float* x = s_obs + row * OBS_LD + in_off;
    float4 b = __ldg((const float4*)(b1 + o0));
    float acc[4] = {b.x, b.y, b.z, b.w};
#pragma unroll
    for (int k = 0; k < K; ++k) {
        float xv = x[k];
        float4 w = __ldg((const float4*)(W1 + k * 32 + o0));
        acc[0] = fmaf(xv, w.x, acc[0]);
        acc[1] = fmaf(xv, w.y, acc[1]);
        acc[2] = fmaf(xv, w.z, acc[2]);
        acc[3] = fmaf(xv, w.w, acc[3]);
    }
    u32 hw[2], lw[2];
    split2(lrelu(acc[0]), lrelu(acc[1]), hw[0], lw[0]);
    split2(lrelu(acc[2]), lrelu(acc[3]), hw[1], lw[1]);
    u32 off = swa(0, row, o0 >> 3) + ((o0 & 4) << 1);
    *(uint2*)(smc + AENC_H + slot * 2048 + off) = make_uint2(hw[0], hw[1]);
    *(uint2*)(smc + AENC_L + slot * 2048 + off) = make_uint2(lw[0], lw[1]);
}

// ======================= HMMA pi GEMM (A tile-direct, B register-direct) ====
// A: hi/lo bf16 tiles at aBase (hi) / aBase+2048 (lo), chunk stride 4096.
// B prefetch interleaved at half-chunk granularity (reuses consumed regs).
// OT=true: output as hi/lo tiles at oBase. OT=false: fp32 sOut.
template <bool OT, int Kt>
__device__ void pi_gemm(u32 aBase, const u32* __restrict__ Bf,
                        const float* __restrict__ sBias,
                        float* __restrict__ sOut, int ldo, u32 oBase,
                        char* smc, u32 sbase, int tid) {
    const int g = tid >> 5, lane = tid & 31;
    const int n0w = g * 32;
    const int fr = ((lane >> 3) & 1) * 8 + (lane & 7);
    const int fu = lane >> 4;
    const int NKS = Kt >> 4, NCh = Kt >> 5;

    u32 adAh[2][2], adAl[2][2];
#pragma unroll
    for (int ks = 0; ks < 2; ++ks) {
        int ua = ks * 2 + fu;
#pragma unroll
        for (int t = 0; t < 2; ++t) {
            int rm = t * 16 + fr;
            adAh[ks][t] = sbase + swa(aBase, rm, ua);
            adAl[ks][t] = sbase + swa(aBase + 2048, rm, ua);
        }
    }
    const u32* bfp = Bf + (long)g * NKS * 512;

    float d[2][4][4];
#pragma unroll
    for (int i = 0; i < 2; ++i)
#pragma unroll
        for (int j = 0; j < 4; ++j)
#pragma unroll
            for (int q = 0; q < 4; ++q) d[i][j][q] = 0.f;

    __syncthreads();   // A tiles ready

    uint4 bq[8];
    LOADFC(bq, bfp, lane);
    LOADFC(bq + 4, bfp + 512, lane);

    for (int kc = 0; kc < NCh; ++kc) {
        const u32 aoff = (u32)(kc * 4096);
        const u32* np = bfp + (2 * (kc + 1)) * 512;
        // ---- ks = 0 (consumes bq[0..3])
        {
            u32 ah[2][4], al[2][4];
#pragma unroll
            for (int t = 0; t < 2; ++t) {
                ldm_x4(ah[t], adAh[0][t] + aoff);
                ldm_x4(al[t], adAl[0][t] + aoff);
            }
            const u32* bb = (const u32*)bq;
#pragma unroll
            for (int mt = 0; mt < 2; ++mt)
#pragma unroll
                for (int nt = 0; nt < 4; ++nt) {
                    mma16816(d[mt][nt], ah[mt], bb[2 * nt], bb[2 * nt + 1]);
                    mma16816(d[mt][nt], ah[mt], bb[8 + 2 * nt], bb[8 + 2 * nt + 1]);
                    mma16816(d[mt][nt], al[mt], bb[2 * nt], bb[2 * nt + 1]);
                }
        }
        if (kc + 1 < NCh) LOADFC(bq, np, lane);      // prefetch next ks=0 half
        // ---- ks = 1 (consumes bq[4..7])
        {
            u32 ah[2][4], al[2][4];
#pragma unroll
            for (int t = 0; t < 2; ++t) {
                ldm_x4(ah[t], adAh[1][t] + aoff);
                ldm_x4(al[t], adAl[1][t] + aoff);
            }
            const u32* bb = (const u32*)(bq + 4);
#pragma unroll
            for (int mt = 0; mt < 2; ++mt)
#pragma unroll
                for (int nt = 0; nt < 4; ++nt) {
                    mma16816(d[mt][nt], ah[mt], bb[2 * nt], bb[2 * nt + 1]);
                    mma16816(d[mt][nt], ah[mt], bb[8 + 2 * nt], bb[8 + 2 * nt + 1]);
                    mma16816(d[mt][nt], al[mt], bb[2 * nt], bb[2 * nt + 1]);
                }
        }
        if (kc + 1 < NCh) LOADFC(bq + 4, np + 512, lane);  // prefetch next ks=1 half
    }
    __syncthreads();   // all A reads done before output overlays
    // ---- readout
#pragma unroll
    for (int mt = 0; mt < 2; ++mt)
#pragma unroll
        for (int nt = 0; nt < 4; ++nt) {
            int lc = nt * 8 + (lane & 3) * 2;
            int col = n0w + lc;
            int row = mt * 16 + (lane >> 2);
            float2 b = *(const float2*)(sBias + col);
            float v0 = lrelu(d[mt][nt][0] + b.x), v1 = lrelu(d[mt][nt][1] + b.y);
            float v2 = lrelu(d[mt][nt][2] + b.x), v3 = lrelu(d[mt][nt][3] + b.y);
            if (OT) {
                u32 off0 = swa(oBase + g * 4096, row, lc >> 3) + (lc & 7) * 2;
                u32 off1 = swa(oBase + g * 4096, row + 8, lc >> 3) + (lc & 7) * 2;
                u32 h0, l0, h1, l1;
                split2(v0, v1, h0, l0);
                split2(v2, v3, h1, l1);
                *(u32*)(smc + off0) = h0;
                *(u32*)(smc + off0 + 2048) = l0;
                *(u32*)(smc + off1) = h1;
                *(u32*)(smc + off1 + 2048) = l1;
            } else {
                *(float2*)(sOut + row * ldo + col) = make_float2(v0, v1);
                *(float2*)(sOut + (row + 8) * ldo + col) = make_float2(v2, v3);
            }
        }
    __syncthreads();
}

// ======================= prep: coalesced fragment-major packing =============
__device__ __forceinline__ u32 fragval(float w0, float w1, int lo) {
    __nv_bfloat16 h0 = __float2bfloat16(w0);
    __nv_bfloat16 h1 = __float2bfloat16(w1);
    if (lo) {
        h0 = __float2bfloat16(w0 - __bfloat162float(h0));
        h1 = __float2bfloat16(w1 - __bfloat162float(h1));
    }
    return pkbf(h0, h1);
}

__global__ void prep_kernel(const float* __restrict__ W1, const float* __restrict__ W2,
                            const float* __restrict__ pW2, const float* __restrict__ eW2,
                            const float* __restrict__ oW2) {
    int i = blockIdx.x * 256 + threadIdx.x;
    if (i < 3 * 8 * 36 * 512) {  // pi1
        int p = i / 147456, r = i % 147456;
        int g = r / 18432; r %= 18432;
        int ks = r / 512; r %= 512;
        int lane = (r >> 2) & 31;
        int s = (r >> 7) * 4 + (r & 3);
        int lo = s >> 3, nt = (s & 7) >> 1, reg = s & 1;
        int n = g * 32 + nt * 8 + (lane >> 2);
        int k = ks * 16 + reg * 8 + 2 * (lane & 3);
        g_B1f[i] = fragval(__ldg(W1 + (p * 576 + k) * 256 + n),
                           __ldg(W1 + (p * 576 + k + 1) * 256 + n), lo);
    }
    if (i < 3 * 8 * 16 * 512) {  // pi2
        int p = i / 65536, r = i % 65536;
        int g = r / 8192; r %= 8192;
        int ks = r / 512; r %= 512;
        int lane = (r >> 2) & 31;
        int s = (r >> 7) * 4 + (r & 3);
        int lo = s >> 3, nt = (s & 7) >> 1, reg = s & 1;
        int n = g * 32 + nt * 8 + (lane >> 2);
        int k = ks * 16 + reg * 8 + 2 * (lane & 3);
        g_B2f[i] = fragval(__ldg(W2 + (p * 256 + k) * 256 + n),
                           __ldg(W2 + (p * 256 + k + 1) * 256 + n), lo);
    }
    if (i < 3 * 54 * 2 * 512) {  // encoder layer2
        int p = i / 55296, r = i % 55296;
        int tile = r / 1024; r %= 1024;
        int ks = r / 512; r %= 512;
        int lane = (r >> 2) & 31;
        int s = (r >> 7) * 4 + (r & 3);
        int lo = s >> 3, nt = (s & 7) >> 1, reg = s & 1;
        int n = nt * 8 + (lane >> 2);
        int k = ks * 16 + reg * 8 + 2 * (lane & 3);
        float w0, w1;
        if (tile < 18) {
            int sn = tile >> 1;
            const float* base = pW2 + ((p * 9 + sn) * 32) * 64 + (tile & 1) * 32 + n;
            w0 = __ldg(base + k * 64);
            w1 = __ldg(base + (k + 1) * 64);
        } else if (tile < 36) {
            int e = (tile - 18) / 9, tt = (tile - 18) % 9;
            const float* base = eW2 + ((p * 2 + e) * 32) * 288 + tt * 32 + n;
            w0 = __ldg(base + k * 288);
            w1 = __ldg(base + (k + 1) * 288);
        } else {
            const float* base = oW2 + (p * 32) * 576 + (tile - 36) * 32 + n;
            w0 = __ldg(base + k * 576);
            w1 = __ldg(base + (k + 1) * 576);
        }
        g_eBf[i] = fragval(w0, w1, lo);
    }
}

// ======================= fused kernel =======================================
__global__ void __launch_bounds__(NT, 2)
mlpac_kernel(const float* __restrict__ obs,
             const float* __restrict__ prop_W1, const float* __restrict__ prop_b1,
             const float* __restrict__ prop_W2, const float* __restrict__ prop_b2,
             const float* __restrict__ ext_W1, const float* __restrict__ ext_b1,
             const float* __restrict__ ext_W2, const float* __restrict__ ext_b2,
             const float* __restrict__ opp_W1, const float* __restrict__ opp_b1,
             const float* __restrict__ opp_W2, const float* __restrict__ opp_b2,
             const float* __restrict__ pi_W1, const float* __restrict__ pi_b1,
             const float* __restrict__ pi_W2, const float* __restrict__ pi_b2,
             const float* __restrict__ pi_W3, const float* __restrict__ pi_b3,
             float* __restrict__ out) {
    extern __shared__ float sm[];
    char* smc = (char*)sm;
    float* s_obs = sm + OBS2_B / 4;
    float* bias_sm = sm + BIAS_B / 4;
    float* cst = sm + CNST_B / 4;
    u32 sbase = smem_u32(sm);

    const int tid = threadIdx.x;
    const int p = blockIdx.y;
    const int row0 = blockIdx.x * TM;

    for (int idx = tid; idx < TM * 12; idx += NT) {
        int r = idx / 12, c = (idx % 12) * 4;
        const float* src = obs + ((long)(row0 + r) * 3 + p) * 48 + c;
        *((float4*)(s_obs + r * OBS_LD + c)) = __ldg((const float4*)src);
    }
    for (int i = tid; i < 576; i += NT) {
        bias_sm[i] = __ldg(prop_b2 + p * 576 + i);
        bias_sm[576 + i] = __ldg(ext_b2 + p * 576 + i);
        bias_sm[1152 + i] = __ldg(opp_b2 + p * 576 + i);
    }
    for (int i = tid; i < 256; i += NT) cst[i] = __ldg(pi_b1 + p * 256 + i);
    for (int i = tid; i < 256; i += NT) cst[256 + i] = __ldg(pi_b2 + p * 256 + i);
    for (int i = tid; i < 768; i += NT) cst[512 + i] = __ldg(pi_W3 + p * 768 + i);
    if (tid < 3) cst[1280 + tid] = __ldg(pi_b3 + p * 3 + tid);

    // ======== encoder: 7 sweeps x 8 tiles; enc stored tile-major ============
    const int ew = tid >> 5;
    const int elane = tid & 31;
    const int efr = ((elane >> 3) & 1) * 8 + (elane & 7);
    const int efu = elane >> 4;
    const u32* ebase = g_eBf + (long)p * 54 * 1024;

    uint4 ebq[8];
    {
        const u32* b0 = ebase + ew * 1024;
        LOADFC(ebq, b0, elane);
        LOADFC(ebq + 4, b0 + 512, elane);
    }
    __syncthreads();   // obs ready

    for (int sweep = 0; sweep < 7; ++sweep) {
        if (sweep == 0) {
#pragma unroll
            for (int s = 0; s < 4; ++s)
                layer1A<2>(s_obs, 2 * s, prop_W1 + p * 576 + s * 64,
                           prop_b1 + p * 288 + s * 32, s, smc, tid);
            __syncthreads();
        } else if (sweep == 1) {
#pragma unroll
            for (int s = 0; s < 4; ++s)
                layer1A<2>(s_obs, 2 * (4 + s), prop_W1 + p * 576 + (4 + s) * 64,
                           prop_b1 + p * 288 + (4 + s) * 32, s, smc, tid);
            __syncthreads();
        } else if (sweep == 2) {
            layer1A<2>(s_obs, 16, prop_W1 + p * 576 + 512, prop_b1 + p * 288 + 256, 0, smc, tid);
            layer1A<6>(s_obs, 18, ext_W1 + p * 384, ext_b1 + p * 64, 1, smc, tid);
            layer1A<6>(s_obs, 24, ext_W1 + p * 384 + 192, ext_b1 + p * 64 + 32, 2, smc, tid);
            layer1A<18>(s_obs, 30, opp_W1 + p * 576, opp_b1 + p * 32, 3, smc, tid);
            __syncthreads();
        }
        int tile = sweep * 8 + ew;
        if (tile < 54) {
            int asl = (tile < 16) ? ((tile >> 1) & 3)
                                  : (tile < 18 ? 0 : (tile < 27 ? 1 : (tile < 36 ? 2 : 3)));
            int etile = (tile < 18) ? tile
                       : (tile < 27 ? tile - 18
                       : (tile < 36 ? 9 + (tile - 27) : tile - 36));
            const u32 tb = (u32)(ENC_T + etile * 4096);
            float d[2][4][4];
#pragma unroll
            for (int mt = 0; mt < 2; ++mt)
#pragma unroll
                for (int j = 0; j < 4; ++j)
#pragma unroll
                    for (int q = 0; q < 4; ++q) d[mt][j][q] = 0.f;
#pragma unroll
            for (int ks = 0; ks < 2; ++ks) {
                int ua = ks * 2 + efu;
                u32 ah[2][4], al[2][4];
#pragma unroll
                for (int mt = 0; mt < 2; ++mt) {
                    ldm_x4(ah[mt], sbase + swa(AENC_H + asl * 2048, mt * 16 + efr, ua));
                    ldm_x4(al[mt], sbase + swa(AENC_L + asl * 2048, mt * 16 + efr, ua));
                }
                const u32* bb = (const u32*)(ebq + ks * 4);
#pragma unroll
                for (int mt = 0; mt < 2; ++mt)
#pragma unroll
                    for (int nt = 0; nt < 4; ++nt) {
                        mma16816(d[mt][nt], ah[mt], bb[2 * nt], bb[2 * nt + 1]);
                        mma16816(d[mt][nt], ah[mt], bb[8 + 2 * nt], bb[8 + 2 * nt + 1]);
                        mma16816(d[mt][nt], al[mt], bb[2 * nt], bb[2 * nt + 1]);
                    }
            }
            {   // prefetch next sweep's fragments
                int ntile = tile + 8;
                if (ntile < 54) {
                    const u32* b0 = ebase + ntile * 1024;
                    LOADFC(ebq, b0, elane);
                    LOADFC(ebq + 4, b0 + 512, elane);
                }
            }
            // ---- readout (tile-major enc)
            if (tile < 36) {
                const bool addm = tile >= 18;
#pragma unroll
                for (int mt = 0; mt < 2; ++mt)
#pragma unroll
                    for (int nt = 0; nt < 4; ++nt) {
                        int lc = nt * 8 + (elane & 3) * 2;
                        int r0 = mt * 16 + (elane >> 2);
                        float2 b = *(const float2*)(bias_sm + tile * 32 + lc);
                        float2 v0 = make_float2(lrelu(d[mt][nt][0] + b.x),
                                                lrelu(d[mt][nt][1] + b.y));
                        float2 v1 = make_float2(lrelu(d[mt][nt][2] + b.x),
                                                lrelu(d[mt][nt][3] + b.y));
                        float* e0 = (float*)(smc + tb + r0 * 128 + lc * 4);
                        float* e1 = (float*)(smc + tb + (r0 + 8) * 128 + lc * 4);
                        if (addm) {
                            float2 o0 = *(float2*)e0, o1 = *(float2*)e1;
                            v0.x += o0.x; v0.y += o0.y; v1.x += o1.x; v1.y += o1.y;
                        }
                        *(float2*)e0 = v0;
                        *(float2*)e1 = v1;
                    }
            } else {
                // opp finalize: enc = prev + lrelu(d + bias); overwrite tile
                // in place with bf16 hi/lo ldmatrix tiles (prev pre-read).
                float2 pv[2][4][2];
#pragma unroll
                for (int mt = 0; mt < 2; ++mt)
#pragma unroll
                    for (int nt = 0; nt < 4; ++nt) {
                        int lc = nt * 8 + (elane & 3) * 2;
                        int r0 = mt * 16 + (elane >> 2);
                        pv[mt][nt][0] = *(float2*)(smc + tb + r0 * 128 + lc * 4);
                        pv[mt][nt][1] = *(float2*)(smc + tb + (r0 + 8) * 128 + lc * 4);
                    }
#pragma unroll
                for (int mt = 0; mt < 2; ++mt)
#pragma unroll
                    for (int nt = 0; nt < 4; ++nt) {
                        int lc = nt * 8 + (elane & 3) * 2;
                        int r0 = mt * 16 + (elane >> 2);
                        float2 b = *(const float2*)(bias_sm + tile * 32 + lc);
                        float v0 = pv[mt][nt][0].x + lrelu(d[mt][nt][0] + b.x);
                        float v1 = pv[mt][nt][0].y + lrelu(d[mt][nt][1] + b.y);
                        float v2 = pv[mt][nt][1].x + lrelu(d[mt][nt][2] + b.x);
                        float v3 = pv[mt][nt][1].y + lrelu(d[mt][nt][3] + b.y);
                        u32 h0, l0, h1, l1;
                        split2(v0, v1, h0, l0);
                        split2(v2, v3, h1, l1);
                        u32 off0 = swa(tb, r0, lc >> 3) + (lc & 7) * 2;
                        u32 off1 = swa(tb, r0 + 8, lc >> 3) + (lc & 7) * 2;
                        *(u32*)(smc + off0) = h0;
                        *(u32*)(smc + off0 + 2048) = l0;
                        *(u32*)(smc + off1) = h1;
                        *(u32*)(smc + off1 + 2048) = l1;
                    }
            }
        }
        __syncthreads();
    }

    // ======== pi MLP (both GEMMs tile-direct, sync-free mainloops) ========
    pi_gemm<true, 576>((u32)ENC_T, g_B1f + (long)p * 147456, cst,
                       (float*)0, 0, (u32)H1T_B, smc, sbase, tid);
    pi_gemm<false, 256>((u32)H1T_B, g_B2f + (long)p * 65536, cst + 256,
                        sm + H2_B / 4, H_LD, 0, smc, sbase, tid);

    if (tid < 96) {
        int row = tid / 3, o = tid - row * 3;
        const float* h2 = sm + H2_B / 4 + row * H_LD;
        float acc = cst[1280 + o];
#pragma unroll 8
        for (int k = 0; k < 256; ++k)
            acc = fmaf(h2[k], cst[512 + k * 3 + o], acc);
        out[((long)(row0 + row) * 3 + p) * 3 + o] = tanhf(acc);
    }
}

extern "C" void kernel_launch(void* const* d_in, const int* in_sizes, int n_in,
                              void* d_out, int out_size) {
    const float* obs = (const float*)d_in[0];
    const float* prop_W1 = (const float*)d_in[1];
    const float* prop_b1 = (const float*)d_in[2];
    const float* prop_W2 = (const float*)d_in[3];
    const float* prop_b2 = (const float*)d_in[4];
    const float* ext_W1 = (const float*)d_in[5];
    const float* ext_b1 = (const float*)d_in[6];
    const float* ext_W2 = (const float*)d_in[7];
    const float* ext_b2 = (const float*)d_in[8];
    const float* opp_W1 = (const float*)d_in[9];
    const float* opp_b1 = (const float*)d_in[10];
    const float* opp_W2 = (const float*)d_in[11];
    const float* opp_b2 = (const float*)d_in[12];
    const float* pi_W1 = (const float*)d_in[13];
    const float* pi_b1 = (const float*)d_in[14];
    const float* pi_W2 = (const float*)d_in[15];
    const float* pi_b2 = (const float*)d_in[16];
    const float* pi_W3 = (const float*)d_in[17];
    const float* pi_b3 = (const float*)d_in[18];
    float* out = (float*)d_out;

    prep_kernel<<<1728, 256>>>(pi_W1, pi_W2, prop_W2, ext_W2, opp_W2);

    cudaFuncSetAttribute(mlpac_kernel, cudaFuncAttributeMaxDynamicSharedMemorySize, SMEM_B);
    dim3 grid(65536 / TM, 3, 1);
    mlpac_kernel<<<grid, NT, SMEM_B>>>(
        obs, prop_W1, prop_b1, prop_W2, prop_b2, ext_W1, ext_b1, ext_W2, ext_b2,
        opp_W1, opp_b1, opp_W2, opp_b2, pi_W1, pi_b1, pi_W2, pi_b2, pi_W3, pi_b3,
        out);
}